// round 10
// baseline (speedup 1.0000x reference)
#include <cuda_runtime.h>
#include <cuda_bf16.h>
#include <cstdint>

constexpr int BB = 16, NN = 2048, DD = 64;
constexpr int TM = 128, TN = 128;
constexpr int THREADS = 256;          // 8 warps; warp w owns rows 16w..16w+15
constexpr int NT = NN / TN;           // 16 K-tiles
constexpr int KW = 36;                // K smem row stride in 4B words (72 bf16)
constexpr int BW = NN / 32;           // 64 bitmask words per row

// 8.4 MB bitmask scratch: bit c of word [row*64 + c/32] = mask[row][c]
__device__ uint32_t g_bits[(size_t)BB * NN * BW];

__device__ __forceinline__ uint32_t packbf(float x, float y) {
    __nv_bfloat162 h = __floats2bfloat162_rn(x, y);   // lo=x, hi=y
    return *reinterpret_cast<uint32_t*>(&h);
}

__device__ __forceinline__ void mma16816(float* c, const uint32_t* a,
                                         uint32_t b0, uint32_t b1) {
    asm volatile(
        "mma.sync.aligned.m16n8k16.row.col.f32.bf16.bf16.f32 "
        "{%0,%1,%2,%3}, {%4,%5,%6,%7}, {%8,%9}, {%0,%1,%2,%3};"
        : "+f"(c[0]), "+f"(c[1]), "+f"(c[2]), "+f"(c[3])
        : "r"(a[0]), "r"(a[1]), "r"(a[2]), "r"(a[3]), "r"(b0), "r"(b1));
}

__device__ __forceinline__ void ldsm_x4(uint32_t& f0, uint32_t& f1,
                                        uint32_t& f2, uint32_t& f3, uint32_t addr) {
    asm volatile("ldmatrix.sync.aligned.m8n8.x4.shared.b16 {%0,%1,%2,%3}, [%4];"
                 : "=r"(f0), "=r"(f1), "=r"(f2), "=r"(f3) : "r"(addr));
}

constexpr unsigned NEGINF_BITS = 0xFF800000u;

// Branch-free top-4 insert of a packed (score|col) float.
// Masked entries become -inf, falling through the network harmlessly.
__device__ __forceinline__ void top4(float (&P)[4], float s, unsigned m, int col) {
    float pf = __int_as_float((__float_as_int(s) & 0xFFFFF800) | col);
    pf = m ? __int_as_float(NEGINF_BITS) : pf;        // SEL, branch-free
    float t1 = fminf(P[0], pf); P[0] = fmaxf(P[0], pf);
    float t2 = fminf(P[1], t1); P[1] = fmaxf(P[1], t1);
    float t3 = fminf(P[2], t2); P[2] = fmaxf(P[2], t2);
    P[3] = fmaxf(P[3], t3);
}

// ---- pre-pass: pack int32 mask -> bitmask (DRAM-streaming, coalesced) ----
__global__ void __launch_bounds__(256, 4)
mask_bitpack_kernel(const int* __restrict__ maski)
{
    const int lane = threadIdx.x & 31;
    const size_t row = (size_t)blockIdx.x * 8 + (threadIdx.x >> 5);
    const int4* src = reinterpret_cast<const int4*>(maski + row * NN);
    uint32_t* dst = g_bits + row * BW;

    #pragma unroll
    for (int i = 0; i < NN / 128; ++i) {              // 16 iterations
        int4 m = __ldcs(src + i * 32 + lane);         // cols 4*(32i+lane)..+3
        uint32_t nib = (unsigned)(m.x != 0)        | ((unsigned)(m.y != 0) << 1)
                     | ((unsigned)(m.z != 0) << 2) | ((unsigned)(m.w != 0) << 3);
        uint32_t c = nib << (4 * (lane & 7));
        c |= __shfl_xor_sync(0xffffffffu, c, 1);
        c |= __shfl_xor_sync(0xffffffffu, c, 2);
        c |= __shfl_xor_sync(0xffffffffu, c, 4);
        if ((lane & 7) == 0) dst[i * 4 + (lane >> 3)] = c;
    }
}

__global__ void __launch_bounds__(THREADS, 2)
attn_hmma_kernel(const float* __restrict__ q, const float* __restrict__ kmat,
                 const float* __restrict__ v,
                 float* __restrict__ attn, float* __restrict__ outp)
{
    __shared__ __align__(16) uint32_t Ksm[TN * KW];   // bf16 K tile [n][d], 18 KB

    const int tid  = threadIdx.x;
    const int warp = tid >> 5;
    const int lane = tid & 31;
    const int g    = lane >> 2;       // 0..7
    const int tig  = lane & 3;        // 0..3
    const int b       = blockIdx.y;
    const int rowBase = blockIdx.x * TM;
    const int r0 = rowBase + warp * 16 + g;
    const int r1 = r0 + 8;

    // ldmatrix per-lane base: matrix m = lane>>3, row r = lane&7
    uint32_t sKsm;
    asm("{ .reg .u64 t; cvta.to.shared.u64 t, %1; cvt.u32.u64 %0, t; }"
        : "=r"(sKsm) : "l"(Ksm));
    const int lm_m  = lane >> 3;
    const int lm_r  = lane & 7;
    const uint32_t lmBase = sKsm + 4u * ((uint32_t)(8 * (lm_m >> 1) + lm_r) * KW
                                         + (uint32_t)(lm_m & 1) * 4u);

    // ---- A fragments (Q rows r0,r1 as bf16), loaded once ----
    uint32_t aF[4][4];
    {
        const float* q0 = q + ((size_t)b * NN + r0) * DD;
        const float* q1 = q + ((size_t)b * NN + r1) * DD;
        #pragma unroll
        for (int s = 0; s < 4; ++s) {
            float2 x0 = *reinterpret_cast<const float2*>(q0 + 16 * s + 2 * tig);
            float2 x1 = *reinterpret_cast<const float2*>(q1 + 16 * s + 2 * tig);
            float2 x2 = *reinterpret_cast<const float2*>(q0 + 16 * s + 2 * tig + 8);
            float2 x3 = *reinterpret_cast<const float2*>(q1 + 16 * s + 2 * tig + 8);
            aF[s][0] = packbf(x0.x, x0.y);
            aF[s][1] = packbf(x1.x, x1.y);
            aF[s][2] = packbf(x2.x, x2.y);
            aF[s][3] = packbf(x3.x, x3.y);
        }
    }

    const float NEGINF = __int_as_float(NEGINF_BITS);
    float p0[4] = {NEGINF, NEGINF, NEGINF, NEGINF};
    float p1[4] = {NEGINF, NEGINF, NEGINF, NEGINF};

    const uint4* bits0 = reinterpret_cast<const uint4*>(g_bits + (size_t)(b * NN + r0) * BW);
    const uint4* bits1 = reinterpret_cast<const uint4*>(g_bits + (size_t)(b * NN + r1) * BW);

    for (int t = 0; t < NT; ++t) {
        if (t) __syncthreads();   // prior tile fully consumed before overwrite

        // mask bit-words for this tile (128 cols = 4 words per row), tiny + broadcast
        const uint4 mw0 = __ldg(bits0 + t);
        const uint4 mw1 = __ldg(bits1 + t);

        // ---- load + convert K tile (row = tid>>1, d-half = (tid&1)*32) ----
        {
            const float4* src = reinterpret_cast<const float4*>(
                kmat + ((size_t)b * NN + t * TN + (tid >> 1)) * DD) + (tid & 1) * 8;
            uint32_t* dst = Ksm + (tid >> 1) * KW + (tid & 1) * 16;
            #pragma unroll
            for (int qt = 0; qt < 2; ++qt) {
                float4 f0 = src[qt * 4 + 0], f1 = src[qt * 4 + 1];
                float4 f2 = src[qt * 4 + 2], f3 = src[qt * 4 + 3];
                uint4 w0 = make_uint4(packbf(f0.x, f0.y), packbf(f0.z, f0.w),
                                      packbf(f1.x, f1.y), packbf(f1.z, f1.w));
                uint4 w1 = make_uint4(packbf(f2.x, f2.y), packbf(f2.z, f2.w),
                                      packbf(f3.x, f3.y), packbf(f3.z, f3.w));
                *reinterpret_cast<uint4*>(dst + qt * 8)     = w0;
                *reinterpret_cast<uint4*>(dst + qt * 8 + 4) = w1;
            }
        }
        __syncthreads();

        #pragma unroll
        for (int jh = 0; jh < 2; ++jh) {
            const int colBase = t * TN + jh * 64;

            // ---- 16 ldmatrix.x4 + 32 HMMA (per jh: 8 LDSM + 16 HMMA) ----
            float c[8][4];
            #pragma unroll
            for (int j = 0; j < 8; ++j)
                #pragma unroll
                for (int e = 0; e < 4; ++e) c[j][e] = 0.f;

            #pragma unroll
            for (int jp = 0; jp < 4; ++jp) {
                const uint32_t aj = lmBase + 4u * (uint32_t)((64 * jh + 16 * jp) * KW);
                #pragma unroll
                for (int s = 0; s < 4; ++s) {
                    uint32_t f0, f1, f2, f3;
                    ldsm_x4(f0, f1, f2, f3, aj + 32u * s);
                    mma16816(c[2 * jp],     aF[s], f0, f1);
                    mma16816(c[2 * jp + 1], aF[s], f2, f3);
                }
            }

            // ---- branch-free top-4 update; mask bits from uint4 words ----
            const uint32_t w0[2] = {jh ? mw0.z : mw0.x, jh ? mw0.w : mw0.y};
            const uint32_t w1[2] = {jh ? mw1.z : mw1.x, jh ? mw1.w : mw1.y};
            #pragma unroll
            for (int jj = 0; jj < 8; ++jj) {
                const int col = colBase + 8 * jj + 2 * tig;
                const int sh  = 8 * (jj & 3) + 2 * tig;        // bit pos in word
                const uint32_t wa = w0[jj >> 2] >> sh;
                const uint32_t wb = w1[jj >> 2] >> sh;
                top4(p0, c[jj][0], wa & 1u, col);
                top4(p0, c[jj][1], wa & 2u, col + 1);
                top4(p1, c[jj][2], wb & 1u, col);
                top4(p1, c[jj][3], wb & 2u, col + 1);
            }
        }
    }

    // ---- exact fp32 rescore of <=4 candidates/lane (round-2-verified order) ----
    auto finish = [&](float (&P)[4], int row) {
        float bE = -__int_as_float(0x7f800000);
        int   bI = 0x7fffffff;
        #pragma unroll
        for (int i = 0; i < 4; ++i) {
            if (P[i] != NEGINF) {
                const int cI = __float_as_int(P[i]) & 0x7FF;
                const float4* qr = reinterpret_cast<const float4*>(q + ((size_t)b * NN + row) * DD);
                const float4* kr = reinterpret_cast<const float4*>(kmat + ((size_t)b * NN + cI) * DD);
                float acc = 0.f;
                #pragma unroll
                for (int j2 = 0; j2 < 16; ++j2) {
                    float4 qa = qr[j2], ka = kr[j2];
                    acc = fmaf(qa.x, ka.x, acc);
                    acc = fmaf(qa.y, ka.y, acc);
                    acc = fmaf(qa.z, ka.z, acc);
                    acc = fmaf(qa.w, ka.w, acc);
                }
                if (acc > bE || (acc == bE && cI < bI)) { bE = acc; bI = cI; }
            }
        }
        #pragma unroll
        for (int off = 1; off < 4; off <<= 1) {
            float oE = __shfl_xor_sync(0xffffffffu, bE, off);
            int   oI = __shfl_xor_sync(0xffffffffu, bI, off);
            if (oE > bE || (oE == bE && oI < bI)) { bE = oE; bI = oI; }
        }
        if (bI == 0x7fffffff) bI = 0;  // safety (all-masked lane set)
        if (tig == 0) attn[((size_t)b * NN + row) * NN + bI] = 1.0f;
        const float4* vs = reinterpret_cast<const float4*>(v + ((size_t)b * NN + bI) * DD);
        float4* dst = reinterpret_cast<float4*>(outp + ((size_t)b * NN + row) * DD);
        #pragma unroll
        for (int j2 = 0; j2 < 4; ++j2) dst[tig * 4 + j2] = vs[tig * 4 + j2];
    };
    finish(p0, r0);
    finish(p1, r1);
}

extern "C" void kernel_launch(void* const* d_in, const int* in_sizes, int n_in,
                              void* d_out, int out_size) {
    const float* q    = (const float*)d_in[0];
    const float* k    = (const float*)d_in[1];
    const float* v    = (const float*)d_in[2];
    const int*   mask = (const int*)d_in[3];

    float* attn = (float*)d_out;                   // [B, N, N]
    float* outp = attn + (size_t)BB * NN * NN;     // [B, N, D]

    // attn is one-hot: zero-fill, kernel scatters a single 1.0 per row
    cudaMemsetAsync(d_out, 0, (size_t)BB * NN * NN * sizeof(float));

    // pre-pass: pack mask into bits (coalesced, DRAM-bound)
    mask_bitpack_kernel<<<BB * NN / 8, 256>>>(mask);

    dim3 grid(NN / TM, BB);
    attn_hmma_kernel<<<grid, THREADS>>>(q, k, v, attn, outp);
}